// round 4
// baseline (speedup 1.0000x reference)
#include <cuda_runtime.h>
#include <math.h>

// Shapes (hardcoded per reference)
#define V  32
#define B  128
#define P  256
#define J  75
#define S2 25
#define F1 500   // fc1 out
#define F2 200   // fc2 out
#define KX 800   // V*S2

// Scratch (device globals: no allocation allowed)
__device__ float g_z [V*B*J];      // SLayer output
__device__ float g_xT[KX*B];       // concat activations, transposed [k][b]
__device__ float g_y1[F1*B];       // fc1 post-BN, transposed [f][b]

__device__ __forceinline__ float warpSum(float v) {
    #pragma unroll
    for (int o = 16; o > 0; o >>= 1) v += __shfl_down_sync(0xffffffffu, v, o);
    return v;
}

// ---------------------------------------------------------------------------
// Kernel 1: transform + SLayer. One block per (v, b-pair). blockDim = 160.
// Ballot compaction; padded to multiple of 8 with sentinels (exp -> 0).
// Points consumed via float4 LDS.128 (register-guaranteed, MLP=4x128b).
__global__ void k_slayer(const float* __restrict__ births, const float* __restrict__ lifetimes,
                         const int* __restrict__ mask, const float* __restrict__ centers,
                         const float* __restrict__ sharpness) {
    int blk = blockIdx.x;           // V * B/2 = 2048
    int v   = blk >> 6;
    int b0  = (blk & 63) << 1;
    __shared__ __align__(16) float sqx[2][P+8], sqy[2][P+8];
    __shared__ int scnt[2];
    int tid = threadIdx.x;

    if (tid < 64) {
        int w = tid >> 5, lane = tid & 31;
        int base = (v*B + b0 + w) * P;
        int cnt = 0;
        #pragma unroll
        for (int c = 0; c < P/32; ++c) {
            int p = c*32 + lane;
            int mv = mask[base + p];
            float bb = births[base + p], ll = lifetimes[base + p];
            float dd = bb + ll + 0.01f;
            const float inv = 0.70710678118654752440f;
            float x = (bb + dd) * inv;
            float y = (dd - bb) * inv;
            if (y <= 0.1f) y = __logf(y * 10.0f) * 0.1f + 0.1f;
            unsigned bal = __ballot_sync(0xffffffffu, mv != 0);
            if (mv) {
                int pos = cnt + __popc(bal & ((1u << lane) - 1u));
                sqx[w][pos] = x; sqy[w][pos] = y;
            }
            cnt += __popc(bal);
        }
        int n8 = (cnt + 7) & ~7;    // pad: sentinel points give exp(-huge)=0
        if (lane < n8 - cnt) { sqx[w][cnt+lane] = 1e18f; sqy[w][cnt+lane] = 1e18f; }
        if (lane == 0) scnt[w] = n8;
    }
    __syncthreads();

    if (tid < 2*J) {
        int w = (tid >= J);
        int j = tid - w*J;
        int n8 = scnt[w];
        int cj = (v*J + j) * 2;
        float cx = centers[cj], cy = centers[cj+1];
        float sx = sharpness[cj];   sx *= sx;
        float sy = sharpness[cj+1]; sy *= sy;
        float acc0 = 0.f, acc1 = 0.f;
        const float4* qx4 = reinterpret_cast<const float4*>(sqx[w]);
        const float4* qy4 = reinterpret_cast<const float4*>(sqy[w]);
        for (int p = 0; p < n8; p += 8) {
            float4 xa = qx4[(p>>2)], xb = qx4[(p>>2)+1];
            float4 ya = qy4[(p>>2)], yb = qy4[(p>>2)+1];
            float dx, dy;
            dx = xa.x-cx; dy = ya.x-cy; acc0 += __expf(-fmaf(sx*dx, dx, sy*dy*dy));
            dx = xa.y-cx; dy = ya.y-cy; acc1 += __expf(-fmaf(sx*dx, dx, sy*dy*dy));
            dx = xa.z-cx; dy = ya.z-cy; acc0 += __expf(-fmaf(sx*dx, dx, sy*dy*dy));
            dx = xa.w-cx; dy = ya.w-cy; acc1 += __expf(-fmaf(sx*dx, dx, sy*dy*dy));
            dx = xb.x-cx; dy = yb.x-cy; acc0 += __expf(-fmaf(sx*dx, dx, sy*dy*dy));
            dx = xb.y-cx; dy = yb.y-cy; acc1 += __expf(-fmaf(sx*dx, dx, sy*dy*dy));
            dx = xb.z-cx; dy = yb.z-cy; acc0 += __expf(-fmaf(sx*dx, dx, sy*dy*dy));
            dx = xb.w-cx; dy = yb.w-cy; acc1 += __expf(-fmaf(sx*dx, dx, sy*dy*dy));
        }
        g_z[(v*B + b0 + w)*J + j] = acc0 + acc1;
    }
}

// ---------------------------------------------------------------------------
// Kernel 2: prew + neighbor stack + stage_1(max) + l1 + BN1 + l2 + ReLU.
// One block per v. blockDim = 480.
__global__ void k_mid(const float* __restrict__ w1, const float* __restrict__ w2,
                      const float* __restrict__ l1_w, const float* __restrict__ l1_b,
                      const float* __restrict__ bn1_g, const float* __restrict__ bn1_b,
                      const float* __restrict__ l2_w, const float* __restrict__ l2_b) {
    int v = blockIdx.x;
    __shared__ float sW[24];
    __shared__ float hh[64*J];       // 19.2 KB
    __shared__ float su[B*S2];       // 12.8 KB
    __shared__ float sl1[S2*J];      // 7.5 KB
    __shared__ float sl2[S2*S2];     // 2.5 KB
    __shared__ float smean[S2], sscale[S2], sbeta[S2], sb1[S2], sb2[S2];
    int tid = threadIdx.x;
    const int NT = 480;

    if (tid < 24) {                  // fused stage_1 weights: W = w2 @ w1
        int g = tid/3, c = tid%3;
        float acc = 0.f;
        #pragma unroll 8
        for (int f = 0; f < 32; ++f)
            acc = fmaf(w2[(v*8+g)*32 + f], w1[(v*32+f)*3 + c], acc);
        sW[tid] = acc;
    }
    for (int i = tid; i < S2*J;  i += NT) sl1[i] = l1_w[v*S2*J  + i];
    for (int i = tid; i < S2*S2; i += NT) sl2[i] = l2_w[v*S2*S2 + i];
    if (tid < S2) { sb1[tid] = l1_b[v*S2+tid]; sb2[tid] = l2_b[v*S2+tid]; sbeta[tid] = bn1_b[v*S2+tid]; }
    __syncthreads();

    int vm = (v + V - 1) & (V - 1), vp = (v + 1) & (V - 1);
    for (int half = 0; half < 2; ++half) {
        int bb0 = half * 64;
        for (int i = tid; i < 64*J; i += NT) {
            int bl = i / J, j = i - bl*J, b = bb0 + bl;
            float z0 = g_z[(vm*B + b)*J + j];
            float z1 = g_z[(v *B + b)*J + j];
            float z2 = g_z[(vp*B + b)*J + j];
            float m = -INFINITY;
            #pragma unroll
            for (int g = 0; g < 8; ++g) {
                float s = fmaf(sW[g*3+2], z2, fmaf(sW[g*3+1], z1, sW[g*3]*z0));
                m = fmaxf(m, s);
            }
            hh[i] = m;
        }
        __syncthreads();
        for (int i = tid; i < S2*64; i += NT) {
            int o = i / 64, bl = i % 64;
            float acc = sb1[o];
            const float* hr = &hh[bl*J];
            const float* wr = &sl1[o*J];
            #pragma unroll 5
            for (int j = 0; j < J; ++j) acc = fmaf(hr[j], wr[j], acc);
            su[(bb0 + bl)*S2 + o] = acc;
        }
        __syncthreads();
    }

    // BN1 stats: one warp per output channel (15 warps)
    int warp = tid >> 5, lane = tid & 31;
    for (int o = warp; o < S2; o += 15) {
        float s = 0.f;
        #pragma unroll
        for (int b = lane; b < B; b += 32) s += su[b*S2 + o];
        s = warpSum(s);
        s = __shfl_sync(0xffffffffu, s, 0);
        float mean = s * (1.f / B);
        float vv = 0.f;
        #pragma unroll
        for (int b = lane; b < B; b += 32) { float d = su[b*S2 + o] - mean; vv = fmaf(d, d, vv); }
        vv = warpSum(vv);
        if (lane == 0) { smean[o] = mean; sscale[o] = bn1_g[v*S2+o] * rsqrtf(vv*(1.f/B) + 1e-5f); }
    }
    __syncthreads();

    for (int i = tid; i < B*S2; i += NT) {
        int o = i % S2;
        su[i] = (su[i] - smean[o]) * sscale[o] + sbeta[o];
    }
    __syncthreads();

    // l2 + ReLU, write transposed [k][b]
    for (int i = tid; i < S2*B; i += NT) {
        int p = i / B, b = i % B;
        float acc = sb2[p];
        const float* ur = &su[b*S2];
        const float* wr = &sl2[p*S2];
        #pragma unroll
        for (int o = 0; o < S2; ++o) acc = fmaf(ur[o], wr[o], acc);
        g_xT[(v*S2 + p)*B + b] = fmaxf(acc, 0.f);
    }
}

// ---------------------------------------------------------------------------
// Kernel 3: fc1 (800->500) + BN2. 5 features/block, split-K (2x400).
// grid = 100, blockDim = 256. Scalar 8-wide prefetch (register MLP=8).
#define FPB 5
__global__ void k_fc1(const float* __restrict__ fc1_w, const float* __restrict__ fc1_b,
                      const float* __restrict__ bn2_g, const float* __restrict__ bn2_b) {
    __shared__ float sw[FPB*KX];     // 16 KB
    __shared__ float part[FPB*B];    // 2.5 KB
    __shared__ float smean[FPB], sscale[FPB];
    int f0 = blockIdx.x * FPB;
    int tid = threadIdx.x;
    int half = tid >> 7, bb = tid & 127;

    for (int i = tid; i < FPB*KX; i += 256) sw[i] = fc1_w[f0*KX + i];
    __syncthreads();

    float a0, a1, a2, a3, a4;
    if (half) { a0=a1=a2=a3=a4=0.f; }
    else { a0=fc1_b[f0]; a1=fc1_b[f0+1]; a2=fc1_b[f0+2]; a3=fc1_b[f0+3]; a4=fc1_b[f0+4]; }
    const float* xb = g_xT + half * (KX/2) * B + bb;
    const float* wb = sw + half * (KX/2);
    #pragma unroll 1
    for (int kc = 0; kc < KX/2; kc += 8) {
        float x0 = xb[(kc+0)*B], x1 = xb[(kc+1)*B], x2 = xb[(kc+2)*B], x3 = xb[(kc+3)*B];
        float x4 = xb[(kc+4)*B], x5 = xb[(kc+5)*B], x6 = xb[(kc+6)*B], x7 = xb[(kc+7)*B];
        #pragma unroll
        for (int u = 0; u < 8; ++u) {
            float xv = (u==0)?x0:(u==1)?x1:(u==2)?x2:(u==3)?x3:(u==4)?x4:(u==5)?x5:(u==6)?x6:x7;
            const float* wr = wb + kc + u;
            a0 = fmaf(wr[0*KX], xv, a0);
            a1 = fmaf(wr[1*KX], xv, a1);
            a2 = fmaf(wr[2*KX], xv, a2);
            a3 = fmaf(wr[3*KX], xv, a3);
            a4 = fmaf(wr[4*KX], xv, a4);
        }
    }
    if (half) {
        part[0*B+bb]=a0; part[1*B+bb]=a1; part[2*B+bb]=a2; part[3*B+bb]=a3; part[4*B+bb]=a4;
    }
    __syncthreads();
    if (!half) {
        part[0*B+bb]+=a0; part[1*B+bb]+=a1; part[2*B+bb]+=a2; part[3*B+bb]+=a3; part[4*B+bb]+=a4;
    }
    __syncthreads();

    // BN2 stats: warp ff reduces feature ff over batch
    int warp = tid >> 5, lane = tid & 31;
    if (warp < FPB) {
        float s = 0.f;
        #pragma unroll
        for (int b = lane; b < B; b += 32) s += part[warp*B + b];
        s = warpSum(s);
        s = __shfl_sync(0xffffffffu, s, 0);
        float mean = s * (1.f / B);
        float vv = 0.f;
        #pragma unroll
        for (int b = lane; b < B; b += 32) { float d = part[warp*B + b] - mean; vv = fmaf(d, d, vv); }
        vv = warpSum(vv);
        if (lane == 0) { smean[warp] = mean; sscale[warp] = bn2_g[f0+warp] * rsqrtf(vv*(1.f/B) + 1e-5f); }
    }
    __syncthreads();

    if (!half) {
        #pragma unroll
        for (int ff = 0; ff < FPB; ++ff)
            g_y1[(f0+ff)*B + bb] = (part[ff*B + bb] - smean[ff]) * sscale[ff] + bn2_b[f0+ff];
    }
}

// ---------------------------------------------------------------------------
// Kernel 4: fc2 (500->200). 2 outputs/block, split-K (2x250).
// grid = 100, blockDim = 256. Scalar 10-wide prefetch (register MLP=10).
#define OPB 2
__global__ void k_fc2(const float* __restrict__ fc2_w, const float* __restrict__ fc2_b,
                      float* __restrict__ out) {
    __shared__ float sw[OPB*F1];     // 4 KB
    __shared__ float part[OPB*B];    // 1 KB
    int o0 = blockIdx.x * OPB;
    int tid = threadIdx.x;
    int half = tid >> 7, bb = tid & 127;

    for (int i = tid; i < OPB*F1; i += 256) sw[i] = fc2_w[o0*F1 + i];
    __syncthreads();

    float a0, a1;
    if (half) { a0 = a1 = 0.f; }
    else { a0 = fc2_b[o0]; a1 = fc2_b[o0+1]; }
    const float* yb = g_y1 + half * (F1/2) * B + bb;
    const float* wb = sw + half * (F1/2);
    #pragma unroll 1
    for (int fc = 0; fc < F1/2; fc += 10) {
        float y0 = yb[(fc+0)*B], y1 = yb[(fc+1)*B], y2 = yb[(fc+2)*B], y3 = yb[(fc+3)*B], y4 = yb[(fc+4)*B];
        float y5 = yb[(fc+5)*B], y6 = yb[(fc+6)*B], y7 = yb[(fc+7)*B], y8 = yb[(fc+8)*B], y9 = yb[(fc+9)*B];
        const float* wr = wb + fc;
        a0 = fmaf(wr[0], y0, a0); a1 = fmaf(wr[F1+0], y0, a1);
        a0 = fmaf(wr[1], y1, a0); a1 = fmaf(wr[F1+1], y1, a1);
        a0 = fmaf(wr[2], y2, a0); a1 = fmaf(wr[F1+2], y2, a1);
        a0 = fmaf(wr[3], y3, a0); a1 = fmaf(wr[F1+3], y3, a1);
        a0 = fmaf(wr[4], y4, a0); a1 = fmaf(wr[F1+4], y4, a1);
        a0 = fmaf(wr[5], y5, a0); a1 = fmaf(wr[F1+5], y5, a1);
        a0 = fmaf(wr[6], y6, a0); a1 = fmaf(wr[F1+6], y6, a1);
        a0 = fmaf(wr[7], y7, a0); a1 = fmaf(wr[F1+7], y7, a1);
        a0 = fmaf(wr[8], y8, a0); a1 = fmaf(wr[F1+8], y8, a1);
        a0 = fmaf(wr[9], y9, a0); a1 = fmaf(wr[F1+9], y9, a1);
    }
    if (half) {
        part[0*B+bb] = a0; part[1*B+bb] = a1;
    }
    __syncthreads();
    if (!half) {
        out[bb*F2 + o0 + 0] = a0 + part[0*B+bb];
        out[bb*F2 + o0 + 1] = a1 + part[1*B+bb];
    }
}

// ---------------------------------------------------------------------------
extern "C" void kernel_launch(void* const* d_in, const int* in_sizes, int n_in,
                              void* d_out, int out_size) {
    const float* births    = (const float*)d_in[0];
    const float* lifetimes = (const float*)d_in[1];
    const int*   mask      = (const int*)  d_in[2];
    const float* centers   = (const float*)d_in[3];
    const float* sharpness = (const float*)d_in[4];
    const float* w1        = (const float*)d_in[5];
    const float* w2        = (const float*)d_in[6];
    const float* l1_w      = (const float*)d_in[7];
    const float* l1_b      = (const float*)d_in[8];
    const float* bn1_g     = (const float*)d_in[9];
    const float* bn1_b     = (const float*)d_in[10];
    const float* l2_w      = (const float*)d_in[11];
    const float* l2_b      = (const float*)d_in[12];
    const float* fc1_w     = (const float*)d_in[13];
    const float* fc1_b     = (const float*)d_in[14];
    const float* bn2_g     = (const float*)d_in[15];
    const float* bn2_b     = (const float*)d_in[16];
    const float* fc2_w     = (const float*)d_in[17];
    const float* fc2_b     = (const float*)d_in[18];
    float* out = (float*)d_out;

    k_slayer<<<V*B/2, 160>>>(births, lifetimes, mask, centers, sharpness);
    k_mid   <<<V, 480>>>(w1, w2, l1_w, l1_b, bn1_g, bn1_b, l2_w, l2_b);
    k_fc1   <<<F1/FPB, 256>>>(fc1_w, fc1_b, bn2_g, bn2_b);
    k_fc2   <<<F2/OPB, 256>>>(fc2_w, fc2_b, out);
}

// round 5
// speedup vs baseline: 1.8509x; 1.8509x over previous
#include <cuda_runtime.h>
#include <math.h>

// Shapes (hardcoded per reference)
#define V  32
#define B  128
#define P  256
#define J  75
#define S2 25
#define F1 500   // fc1 out
#define F2 200   // fc2 out
#define KX 800   // V*S2

// Scratch (device globals: no allocation allowed)
__device__ float g_z [V*B*J];      // SLayer output
__device__ float g_xT[KX*B];       // concat activations, transposed [k][b]
__device__ float g_y1[F1*B];       // fc1 post-BN, transposed [f][b]

__device__ __forceinline__ float warpSum(float v) {
    #pragma unroll
    for (int o = 16; o > 0; o >>= 1) v += __shfl_down_sync(0xffffffffu, v, o);
    return v;
}

// ---------------------------------------------------------------------------
// Kernel 1: transform + SLayer. One block per (v, b-pair). blockDim = 160.
// (R2 version, verbatim — part of the 80.4us run.)
__global__ void k_slayer(const float* __restrict__ births, const float* __restrict__ lifetimes,
                         const int* __restrict__ mask, const float* __restrict__ centers,
                         const float* __restrict__ sharpness) {
    int blk = blockIdx.x;           // V * B/2 = 2048
    int v   = blk >> 6;
    int b0  = (blk & 63) << 1;
    __shared__ float sqx[2][P], sqy[2][P];
    __shared__ int scnt[2];
    int tid = threadIdx.x;

    if (tid < 64) {
        int w = tid >> 5, lane = tid & 31;
        int base = (v*B + b0 + w) * P;
        int cnt = 0;
        #pragma unroll
        for (int c = 0; c < P/32; ++c) {
            int p = c*32 + lane;
            int mv = mask[base + p];
            float bb = births[base + p], ll = lifetimes[base + p];
            float dd = bb + ll + 0.01f;
            const float inv = 0.70710678118654752440f;
            float x = (bb + dd) * inv;
            float y = (dd - bb) * inv;
            if (y <= 0.1f) y = __logf(y * 10.0f) * 0.1f + 0.1f;
            unsigned bal = __ballot_sync(0xffffffffu, mv != 0);
            if (mv) {
                int pos = cnt + __popc(bal & ((1u << lane) - 1u));
                sqx[w][pos] = x; sqy[w][pos] = y;
            }
            cnt += __popc(bal);
        }
        if (lane == 0) scnt[w] = cnt;
    }
    __syncthreads();

    if (tid < 2*J) {
        int w = (tid >= J);
        int j = tid - w*J;
        int n = scnt[w];
        int cj = (v*J + j) * 2;
        float cx = centers[cj], cy = centers[cj+1];
        float sx = sharpness[cj];   sx *= sx;
        float sy = sharpness[cj+1]; sy *= sy;
        float acc = 0.f;
        for (int p = 0; p < n; ++p) {
            float dx = sqx[w][p] - cx;
            float dy = sqy[w][p] - cy;
            float d2 = fmaf(sx*dx, dx, sy*dy*dy);
            acc += __expf(-d2);
        }
        g_z[(v*B + b0 + w)*J + j] = acc;
    }
}

// ---------------------------------------------------------------------------
// Kernel 2: prew + neighbor stack + stage_1(max) + l1 + BN1 + l2 + ReLU.
// One block per v. blockDim = 512. (R2 version, verbatim.)
__global__ void k_mid(const float* __restrict__ w1, const float* __restrict__ w2,
                      const float* __restrict__ l1_w, const float* __restrict__ l1_b,
                      const float* __restrict__ bn1_g, const float* __restrict__ bn1_b,
                      const float* __restrict__ l2_w, const float* __restrict__ l2_b) {
    int v = blockIdx.x;
    __shared__ float sW[24];
    __shared__ float hh[64*J];       // 19.2 KB (half-batch staging)
    __shared__ float su[B*S2];       // 12.8 KB
    __shared__ float sl1[S2*J];      // 7.5 KB
    __shared__ float sl2[S2*S2];     // 2.5 KB
    __shared__ float smean[S2], sscale[S2], sbeta[S2], sb1[S2], sb2[S2];
    int tid = threadIdx.x;

    if (tid < 24) {                  // fused stage_1 weights: W = w2 @ w1
        int g = tid/3, c = tid%3;
        float acc = 0.f;
        #pragma unroll 8
        for (int f = 0; f < 32; ++f)
            acc = fmaf(w2[(v*8+g)*32 + f], w1[(v*32+f)*3 + c], acc);
        sW[tid] = acc;
    }
    for (int i = tid; i < S2*J;  i += 512) sl1[i] = l1_w[v*S2*J  + i];
    for (int i = tid; i < S2*S2; i += 512) sl2[i] = l2_w[v*S2*S2 + i];
    if (tid < S2) { sb1[tid] = l1_b[v*S2+tid]; sb2[tid] = l2_b[v*S2+tid]; sbeta[tid] = bn1_b[v*S2+tid]; }
    __syncthreads();

    int vm = (v + V - 1) & (V - 1), vp = (v + 1) & (V - 1);
    for (int half = 0; half < 2; ++half) {
        int bb0 = half * 64;
        for (int i = tid; i < 64*J; i += 512) {
            int bl = i / J, j = i % J, b = bb0 + bl;
            float z0 = g_z[(vm*B + b)*J + j];
            float z1 = g_z[(v *B + b)*J + j];
            float z2 = g_z[(vp*B + b)*J + j];
            float m = -INFINITY;
            #pragma unroll
            for (int g = 0; g < 8; ++g) {
                float s = fmaf(sW[g*3+2], z2, fmaf(sW[g*3+1], z1, sW[g*3]*z0));
                m = fmaxf(m, s);
            }
            hh[i] = m;
        }
        __syncthreads();
        for (int i = tid; i < S2*64; i += 512) {
            int o = i / 64, bl = i % 64;
            float acc = sb1[o];
            const float* hr = &hh[bl*J];
            const float* wr = &sl1[o*J];
            #pragma unroll 5
            for (int j = 0; j < J; ++j) acc = fmaf(hr[j], wr[j], acc);
            su[(bb0 + bl)*S2 + o] = acc;
        }
        __syncthreads();
    }

    // BN1 stats: one warp per output channel
    int warp = tid >> 5, lane = tid & 31;
    for (int o = warp; o < S2; o += 16) {
        float s = 0.f;
        #pragma unroll
        for (int b = lane; b < B; b += 32) s += su[b*S2 + o];
        s = warpSum(s);
        s = __shfl_sync(0xffffffffu, s, 0);
        float mean = s * (1.f / B);
        float vv = 0.f;
        #pragma unroll
        for (int b = lane; b < B; b += 32) { float d = su[b*S2 + o] - mean; vv = fmaf(d, d, vv); }
        vv = warpSum(vv);
        if (lane == 0) { smean[o] = mean; sscale[o] = bn1_g[v*S2+o] * rsqrtf(vv*(1.f/B) + 1e-5f); }
    }
    __syncthreads();

    for (int i = tid; i < B*S2; i += 512) {
        int o = i % S2;
        su[i] = (su[i] - smean[o]) * sscale[o] + sbeta[o];
    }
    __syncthreads();

    // l2 + ReLU, write transposed [k][b]
    for (int i = tid; i < S2*B; i += 512) {
        int p = i / B, b = i % B;
        float acc = sb2[p];
        const float* ur = &su[b*S2];
        const float* wr = &sl2[p*S2];
        #pragma unroll
        for (int o = 0; o < S2; ++o) acc = fmaf(ur[o], wr[o], acc);
        g_xT[(v*S2 + p)*B + b] = fmaxf(acc, 0.f);
    }
}

// ---------------------------------------------------------------------------
// Kernel 3: fc1 (800->500) + BN2. 5 features/block, 8-way k-split in-block.
// grid = 100, blockDim = 1024 (32 warps/SM -> latency hidden by occupancy).
#define FPB 5
__global__ void __launch_bounds__(1024, 1)
k_fc1(const float* __restrict__ fc1_w, const float* __restrict__ fc1_b,
      const float* __restrict__ bn2_g, const float* __restrict__ bn2_b) {
    __shared__ float sw[FPB*KX];        // 16 KB
    __shared__ float part[8*FPB*B];     // 20 KB
    __shared__ float smean[FPB], sscale[FPB];
    int f0 = blockIdx.x * FPB;
    int tid = threadIdx.x;
    int ks = tid >> 7, bb = tid & 127;  // ks in 0..7

    for (int i = tid; i < FPB*KX; i += 1024) sw[i] = fc1_w[f0*KX + i];
    __syncthreads();

    float acc[FPB];
    #pragma unroll
    for (int ff = 0; ff < FPB; ++ff) acc[ff] = (ks == 0) ? fc1_b[f0+ff] : 0.f;
    const float* xb = g_xT + ks * 100 * B + bb;   // 100 rows per slice
    const float* wb = sw + ks * 100;
    #pragma unroll 1
    for (int kc = 0; kc < 100; kc += 5) {
        float xv[5];
        #pragma unroll
        for (int u = 0; u < 5; ++u) xv[u] = xb[(kc+u)*B];
        #pragma unroll
        for (int u = 0; u < 5; ++u) {
            #pragma unroll
            for (int ff = 0; ff < FPB; ++ff)
                acc[ff] = fmaf(wb[ff*KX + kc + u], xv[u], acc[ff]);
        }
    }
    #pragma unroll
    for (int ff = 0; ff < FPB; ++ff) part[(ks*FPB + ff)*B + bb] = acc[ff];
    __syncthreads();
    // deterministic tree combine over ks
    if (ks < 4) {
        #pragma unroll
        for (int ff = 0; ff < FPB; ++ff)
            part[(ks*FPB + ff)*B + bb] += part[((ks+4)*FPB + ff)*B + bb];
    }
    __syncthreads();
    if (ks < 2) {
        #pragma unroll
        for (int ff = 0; ff < FPB; ++ff)
            part[(ks*FPB + ff)*B + bb] += part[((ks+2)*FPB + ff)*B + bb];
    }
    __syncthreads();
    if (ks == 0) {
        #pragma unroll
        for (int ff = 0; ff < FPB; ++ff)
            part[ff*B + bb] += part[(FPB + ff)*B + bb];
    }
    __syncthreads();

    // BN2 stats: warp ff reduces feature ff over batch
    int warp = tid >> 5, lane = tid & 31;
    if (warp < FPB) {
        float s = 0.f;
        #pragma unroll
        for (int b = lane; b < B; b += 32) s += part[warp*B + b];
        s = warpSum(s);
        s = __shfl_sync(0xffffffffu, s, 0);
        float mean = s * (1.f / B);
        float vv = 0.f;
        #pragma unroll
        for (int b = lane; b < B; b += 32) { float d = part[warp*B + b] - mean; vv = fmaf(d, d, vv); }
        vv = warpSum(vv);
        if (lane == 0) { smean[warp] = mean; sscale[warp] = bn2_g[f0+warp] * rsqrtf(vv*(1.f/B) + 1e-5f); }
    }
    __syncthreads();

    if (ks == 0) {
        #pragma unroll
        for (int ff = 0; ff < FPB; ++ff)
            g_y1[(f0+ff)*B + bb] = (part[ff*B + bb] - smean[ff]) * sscale[ff] + bn2_b[f0+ff];
    }
}

// ---------------------------------------------------------------------------
// Kernel 4: fc2 (500->200). 2 outputs/block, 4-way k-split in-block.
// grid = 100, blockDim = 512.
#define OPB 2
__global__ void __launch_bounds__(512, 2)
k_fc2(const float* __restrict__ fc2_w, const float* __restrict__ fc2_b,
      float* __restrict__ out) {
    __shared__ float sw[OPB*F1];        // 4 KB
    __shared__ float part[4*OPB*B];     // 4 KB
    int o0 = blockIdx.x * OPB;
    int tid = threadIdx.x;
    int ks = tid >> 7, bb = tid & 127;  // ks in 0..3

    for (int i = tid; i < OPB*F1; i += 512) sw[i] = fc2_w[o0*F1 + i];
    __syncthreads();

    float a0 = (ks == 0) ? fc2_b[o0]   : 0.f;
    float a1 = (ks == 0) ? fc2_b[o0+1] : 0.f;
    const float* yb = g_y1 + ks * 125 * B + bb;   // 125 rows per slice
    const float* wb = sw + ks * 125;
    #pragma unroll 1
    for (int fc = 0; fc < 125; fc += 5) {
        float yv[5];
        #pragma unroll
        for (int u = 0; u < 5; ++u) yv[u] = yb[(fc+u)*B];
        #pragma unroll
        for (int u = 0; u < 5; ++u) {
            a0 = fmaf(wb[fc+u],      yv[u], a0);
            a1 = fmaf(wb[F1+fc+u],   yv[u], a1);
        }
    }
    part[(ks*OPB + 0)*B + bb] = a0;
    part[(ks*OPB + 1)*B + bb] = a1;
    __syncthreads();
    if (ks < 2) {
        #pragma unroll
        for (int oo = 0; oo < OPB; ++oo)
            part[(ks*OPB + oo)*B + bb] += part[((ks+2)*OPB + oo)*B + bb];
    }
    __syncthreads();
    if (ks == 0) {
        out[bb*F2 + o0 + 0] = part[0*B + bb] + part[(OPB+0)*B + bb];
        out[bb*F2 + o0 + 1] = part[1*B + bb] + part[(OPB+1)*B + bb];
    }
}

// ---------------------------------------------------------------------------
extern "C" void kernel_launch(void* const* d_in, const int* in_sizes, int n_in,
                              void* d_out, int out_size) {
    const float* births    = (const float*)d_in[0];
    const float* lifetimes = (const float*)d_in[1];
    const int*   mask      = (const int*)  d_in[2];
    const float* centers   = (const float*)d_in[3];
    const float* sharpness = (const float*)d_in[4];
    const float* w1        = (const float*)d_in[5];
    const float* w2        = (const float*)d_in[6];
    const float* l1_w      = (const float*)d_in[7];
    const float* l1_b      = (const float*)d_in[8];
    const float* bn1_g     = (const float*)d_in[9];
    const float* bn1_b     = (const float*)d_in[10];
    const float* l2_w      = (const float*)d_in[11];
    const float* l2_b      = (const float*)d_in[12];
    const float* fc1_w     = (const float*)d_in[13];
    const float* fc1_b     = (const float*)d_in[14];
    const float* bn2_g     = (const float*)d_in[15];
    const float* bn2_b     = (const float*)d_in[16];
    const float* fc2_w     = (const float*)d_in[17];
    const float* fc2_b     = (const float*)d_in[18];
    float* out = (float*)d_out;

    k_slayer<<<V*B/2, 160>>>(births, lifetimes, mask, centers, sharpness);
    k_mid   <<<V, 512>>>(w1, w2, l1_w, l1_b, bn1_g, bn1_b, l2_w, l2_b);
    k_fc1   <<<F1/FPB, 1024>>>(fc1_w, fc1_b, bn2_g, bn2_b);
    k_fc2   <<<F2/OPB, 512>>>(fc2_w, fc2_b, out);
}